// round 17
// baseline (speedup 1.0000x reference)
#include <cuda_runtime.h>
#include <cuda_fp16.h>
#include <cstdint>

// Problem constants
#define D       256
#define BATCH   1024
#define TSTEPS  1024
#define CHUNK   128
#define MAT     (D * D)
#define NCTA    512                // persistent preamble grid (guaranteed resident)

// ---------------------------------------------------------------------------
// Static device scratch
// ---------------------------------------------------------------------------
__device__ float g_A [MAT];                   // A = kernel * DT
__device__ float g_T1[MAT];                   // D2, later P512
__device__ float g_T2[MAT];                   // D1, later P256
__device__ float g_X [4 * MAT];               // A2/E^896, E^384, E^640, E^768
__device__ float g_P [(CHUNK + 1) * MAT];     // P[i] = E^i fp32, i=1..128
__device__ unsigned g_bar;                    // global barrier counter (reset by fill)
// fp16 operands, pre-tiled + pre-swizzled (XOR-8 on 16B groups) for ldmatrix:
__device__ uint4 g_PB[128 * 4 * 2048];        // B^T tiles (hi only), 16 MB
__device__ uint4 g_ZH[64 * 4 * 1024];         // A tiles (hi only), 4 MB

// ---------------------------------------------------------------------------
// Helpers
// ---------------------------------------------------------------------------
__device__ __forceinline__ uint32_t smem_u32(const void* p) {
    uint32_t a;
    asm("{ .reg .u64 t; cvta.to.shared.u64 t, %1; cvt.u32.u64 %0, t; }"
        : "=r"(a) : "l"(p));
    return a;
}
__device__ __forceinline__ void fma2(unsigned long long& d,
                                     unsigned long long a,
                                     unsigned long long b) {
    asm("fma.rn.f32x2 %0, %1, %2, %0;" : "+l"(d) : "l"(a), "l"(b));
}
__device__ __forceinline__ unsigned long long dup2(float x) {
    unsigned long long r;
    asm("mov.b64 %0, {%1, %1};" : "=l"(r) : "f"(x));
    return r;
}
__device__ __forceinline__ void ldsm4(uint32_t* r, uint32_t addr) {
    asm volatile("ldmatrix.sync.aligned.m8n8.x4.shared.b16 {%0,%1,%2,%3}, [%4];"
                 : "=r"(r[0]), "=r"(r[1]), "=r"(r[2]), "=r"(r[3]) : "r"(addr));
}
__device__ __forceinline__ void mma16816h(float* d, const uint32_t* a,
                                          uint32_t b0, uint32_t b1) {
    asm volatile(
        "mma.sync.aligned.m16n8k16.row.col.f32.f16.f16.f32 "
        "{%0,%1,%2,%3}, {%4,%5,%6,%7}, {%8,%9}, {%0,%1,%2,%3};"
        : "+f"(d[0]), "+f"(d[1]), "+f"(d[2]), "+f"(d[3])
        : "r"(a[0]), "r"(a[1]), "r"(a[2]), "r"(a[3]), "r"(b0), "r"(b1));
}
#define CP16(dst, src) \
    asm volatile("cp.async.cg.shared.global [%0], [%1], 16;" \
                 :: "r"(dst), "l"(src))
#define CP_COMMIT() asm volatile("cp.async.commit_group;" ::: "memory")
#define CP_WAIT1()  asm volatile("cp.async.wait_group 1;" ::: "memory")
#define CP_WAIT0()  asm volatile("cp.async.wait_group 0;" ::: "memory")

__device__ __forceinline__ uint32_t packh2(__half a, __half b) {
    __half_raw ar = *(__half_raw*)&a, br = *(__half_raw*)&b;
    return (uint32_t)ar.x | ((uint32_t)br.x << 16);
}

// Global barrier (monotonic counter; reset to 0 by fill_kernel each run).
__device__ __forceinline__ void gbar(unsigned& target) {
    __syncthreads();
    target += NCTA;
    if (threadIdx.x == 0) {
        __threadfence();
        atomicAdd(&g_bar, 1u);
        unsigned v;
        for (;;) {
            asm volatile("ld.global.cg.u32 %0, [%1];" : "=r"(v) : "l"(&g_bar));
            if (v >= target) break;
            __nanosleep(64);
        }
    }
    __syncthreads();
}

// ---------------------------------------------------------------------------
// 32x64x256 half-tile FFMA2 GEMM (M-half of a 64x64 tile), BK=32, 128 thr,
// 4x4 microtile (half the per-thread work of the old 8x4 -> ~2x lower latency).
// mode 0: C = acc. mode 1 (DIAG): C = acc + c0*I + c1*A.
// mode 2 (ZEMIT): emit fp16(acc * 2^-6) into g_ZH (pre-swizzled).
// ---------------------------------------------------------------------------
__device__ __noinline__ void mm64h(
    float (*As)[40], float (*Bs)[64],
    const float* A, const float* B, float* C,
    int bM, int bN, int mhalf, int mode, float c0, float c1, int zmt, int rowbase)
{
    const int tid = threadIdx.x;
    const int tx = tid & 15, ty = tid >> 4;      // n: 16x4, m: 8x4

    unsigned long long acc[4][2];
#pragma unroll
    for (int i = 0; i < 4; ++i) { acc[i][0] = 0ull; acc[i][1] = 0ull; }

    const int a_r = tid >> 2, a_k = (tid & 3) * 8;   // 32 rows x 32 k
    const int b_k = tid >> 2, n0  = (tid & 3) * 16;  // 32 k x 64 n

    const int Arow = bM * 64 + mhalf * 32;
    const float* Ap = A + (size_t)(Arow + a_r) * D + a_k;
    const float* Bp = B + (size_t)b_k * D + bN * 64 + n0;

    float4 pa[2], pb[4];
#pragma unroll
    for (int j = 0; j < 2; ++j) pa[j] = __ldcg((const float4*)(Ap + j * 4));
#pragma unroll
    for (int j = 0; j < 4; ++j) pb[j] = __ldcg((const float4*)(Bp + j * 4));

    for (int kt = 0; kt < 8; ++kt) {
#pragma unroll
        for (int j = 0; j < 2; ++j) {
            As[a_k + j * 4 + 0][a_r] = pa[j].x;
            As[a_k + j * 4 + 1][a_r] = pa[j].y;
            As[a_k + j * 4 + 2][a_r] = pa[j].z;
            As[a_k + j * 4 + 3][a_r] = pa[j].w;
        }
#pragma unroll
        for (int j = 0; j < 4; ++j)
            *(float4*)&Bs[b_k][n0 + j * 4] = pb[j];
        __syncthreads();

        if (kt < 7) {
#pragma unroll
            for (int j = 0; j < 2; ++j)
                pa[j] = __ldcg((const float4*)(Ap + (kt + 1) * 32 + j * 4));
#pragma unroll
            for (int j = 0; j < 4; ++j)
                pb[j] = __ldcg((const float4*)(Bp + (size_t)(kt + 1) * 32 * D + j * 4));
        }

#pragma unroll
        for (int kk = 0; kk < 32; ++kk) {
            float4 a0 = *(const float4*)&As[kk][ty * 4];
            ulonglong2 bq = *(const ulonglong2*)&Bs[kk][tx * 4];
            float a[4] = {a0.x, a0.y, a0.z, a0.w};
#pragma unroll
            for (int i = 0; i < 4; ++i) {
                unsigned long long aa = dup2(a[i]);
                fma2(acc[i][0], aa, bq.x);
                fma2(acc[i][1], aa, bq.y);
            }
        }
        __syncthreads();
    }

#pragma unroll
    for (int i = 0; i < 4; ++i) {
        int row = Arow + ty * 4 + i;
        int col = bN * 64 + tx * 4;
        union { ulonglong2 u; float f[4]; } v;
        v.u.x = acc[i][0]; v.u.y = acc[i][1];
        if (mode == 0) {
            *(ulonglong2*)(C + (size_t)row * D + col) = v.u;
        } else if (mode == 1) {
#pragma unroll
            for (int q = 0; q < 4; ++q) {
                float e = v.f[q] + c1 * __ldcg(g_A + (size_t)row * D + col + q);
                if (row == col + q) e += c0;
                v.f[q] = e;
            }
            *(ulonglong2*)(C + (size_t)row * D + col) = v.u;
        } else {  // ZEMIT: fp16(val * 2^-6) -> g_ZH
            __half h0 = __float2half(v.f[0] * 0.015625f);
            __half h1 = __float2half(v.f[1] * 0.015625f);
            __half h2 = __float2half(v.f[2] * 0.015625f);
            __half h3 = __float2half(v.f[3] * 0.015625f);
            int rowloc = rowbase + ty * 4 + i;
            int g = tx >> 1;
            int du = rowloc * 8 + (g ^ (rowloc & 7));
            uint2* p = (uint2*)((char*)(g_ZH + (size_t)(zmt * 4 + bN) * 1024 + du)
                                + (tx & 1) * 8);
            *p = make_uint2(packh2(h0, h1), packh2(h2, h3));
        }
    }
}

// convB job: power p, kchunk c -> fp16(P^p[k][n] * 2^-2) transposed+swizzled
__device__ __forceinline__ void convB_job(int p, int c) {
    for (int w = threadIdx.x; w < 2048; w += 128) {
        int n = w & 255, g = w >> 8;
        const float* src = g_P + (size_t)p * MAT + (size_t)(c * 64 + g * 8) * D + n;
        __half h[8];
#pragma unroll
        for (int e = 0; e < 8; ++e)
            h[e] = __float2half(__ldcg(src + (size_t)e * D) * 0.25f);
        uint4 H;
        H.x = packh2(h[0], h[1]); H.y = packh2(h[2], h[3]);
        H.z = packh2(h[4], h[5]); H.w = packh2(h[6], h[7]);
        g_PB[(size_t)((p - 1) * 4 + c) * 2048 + n * 8 + (g ^ (n & 7))] = H;
    }
}

// z0 conv job: mtile (0..7), kchunk c -> fp16(z0 * 2^-6) tiles
__device__ __forceinline__ void convZ0_job(const float* z0, int mtile, int c) {
    for (int w = threadIdx.x; w < 1024; w += 128) {
        int row = w >> 3, g = w & 7;
        const float* src = z0 + (size_t)(mtile * 128 + row) * D + c * 64 + g * 8;
        __half h[8];
#pragma unroll
        for (int e = 0; e < 8; ++e) h[e] = __float2half(src[e] * 0.015625f);
        uint4 H;
        H.x = packh2(h[0], h[1]); H.y = packh2(h[2], h[3]);
        H.z = packh2(h[4], h[5]); H.w = packh2(h[6], h[7]);
        g_ZH[(size_t)(mtile * 4 + c) * 1024 + row * 8 + (g ^ (row & 7))] = H;
    }
}

// ---------------------------------------------------------------------------
// Persistent preamble with half-tile jobs (2x lower stage latency):
// prep -> Horner-expm(3) -> doubling(7, convB overlapped) -> P256(+convB)
// -> P512 -> Q1 -> Q2 -> Z(ZEMIT)+z0conv. 15 barriers.
// ---------------------------------------------------------------------------
__global__ __launch_bounds__(128, 4)
void preamble_kernel(const float* __restrict__ z0, const float* __restrict__ kern) {
    __shared__ float As[32][40];
    __shared__ float Bs[32][64];
    const int cta = blockIdx.x;
    const int tid = threadIdx.x;
    unsigned target = 0;

    // stage 0: A = kern*DT ; D1 = I/24 + A/120 -> g_T2   (65536 thr = MAT)
    {
        int idx = cta * 128 + tid;
        float a = kern[idx] * 0.01f;
        g_A[idx] = a;
        int r = idx >> 8, c = idx & 255;
        g_T2[idx] = (r == c ? (1.f / 24.f) : 0.f) + a * (1.f / 120.f);
    }
    gbar(target);

    // stage 1: A2 = A*A -> g_X[0]   (32 half-jobs)
    for (int j = cta; j < 32; j += NCTA) {
        int h = j & 1, t = j >> 1;
        mm64h(As, Bs, g_A, g_A, g_X, t >> 2, t & 3, h, 0, 0.f, 0.f, 0, 0);
    }
    gbar(target);

    // stage 2: D2 = A2*D1 + I/2 + A/6 -> g_T1
    for (int j = cta; j < 32; j += NCTA) {
        int h = j & 1, t = j >> 1;
        mm64h(As, Bs, g_X, g_T2, g_T1, t >> 2, t & 3, h, 1, 0.5f, 1.f / 6.f, 0, 0);
    }
    gbar(target);

    // stage 3: E = A2*D2 + I + A -> g_P[1]
    for (int j = cta; j < 32; j += NCTA) {
        int h = j & 1, t = j >> 1;
        mm64h(As, Bs, g_X, g_T1, g_P + MAT, t >> 2, t & 3, h, 1, 1.f, 1.f, 0, 0);
    }
    gbar(target);

    // doubling s=0..6 (m=2^s): P[m+i] = P[m]*P[i]; convB of powers (m/2, m]
    for (int s = 0; s < 7; ++s) {
        int m = 1 << s;
        int nmm = 32 * m;
        int ncv = (s == 0) ? 4 : 2 * m;
        for (int j = cta; j < nmm + ncv; j += NCTA) {
            if (j < nmm) {
                int h = j & 1, jm = j >> 1;
                int i = 1 + (jm >> 4), t = jm & 15;
                mm64h(As, Bs, g_P + (size_t)m * MAT, g_P + (size_t)i * MAT,
                      g_P + (size_t)(m + i) * MAT, t >> 2, t & 3, h, 0, 0.f, 0.f, 0, 0);
            } else {
                int e = j - nmm;
                int p = (s == 0) ? 1 : (m / 2 + 1 + (e >> 2));
                convB_job(p, e & 3);
            }
        }
        gbar(target);
    }

    // P256 = P128*P128 -> g_T2 (D1 dead)  + convB of powers 65..128
    for (int j = cta; j < 32 + 256; j += NCTA) {
        if (j < 32) {
            int h = j & 1, t = j >> 1;
            mm64h(As, Bs, g_P + (size_t)128 * MAT, g_P + (size_t)128 * MAT, g_T2,
                  t >> 2, t & 3, h, 0, 0.f, 0.f, 0, 0);
        } else { int e = j - 32; convB_job(65 + (e >> 2), e & 3); }
    }
    gbar(target);

    // P512 = P256*P256 -> g_T1 (D2 dead)
    for (int j = cta; j < 32; j += NCTA) {
        int h = j & 1, t = j >> 1;
        mm64h(As, Bs, g_T2, g_T2, g_T1, t >> 2, t & 3, h, 0, 0.f, 0.f, 0, 0);
    }
    gbar(target);

    // Q1: E^384 = P128*P256 -> X1 ; E^640 = P128*P512 -> X2 ; E^768 = P256*P512 -> X3
    for (int j = cta; j < 96; j += NCTA) {
        int h = j & 1, jm = j >> 1;
        int q = jm >> 4, t = jm & 15;
        const float* Aq = (q == 2) ? g_T2 : g_P + (size_t)128 * MAT;
        const float* Bq = (q == 0) ? g_T2 : g_T1;
        mm64h(As, Bs, Aq, Bq, g_X + (size_t)(q + 1) * MAT,
              t >> 2, t & 3, h, 0, 0.f, 0.f, 0, 0);
    }
    gbar(target);

    // Q2: E^896 = E^384 * P512 -> X0 (A2 dead)
    for (int j = cta; j < 32; j += NCTA) {
        int h = j & 1, t = j >> 1;
        mm64h(As, Bs, g_X + MAT, g_T1, g_X, t >> 2, t & 3, h, 0, 0.f, 0.f, 0, 0);
    }
    gbar(target);

    // Z stage: Z_j = z0 * Q_j (j=1..7), fp16 emitted directly; + z0's own tiles.
    for (int j = cta; j < 896 + 32; j += NCTA) {
        if (j < 896) {
            int h = j & 1, jm = j >> 1;
            int zj = 1 + (jm >> 6), t = jm & 63;
            int bM = t >> 2, bN = t & 3;
            const float* Q =
                (zj == 1) ? g_P + (size_t)128 * MAT :
                (zj == 2) ? g_T2 :
                (zj == 3) ? g_X + (size_t)1 * MAT :
                (zj == 4) ? g_T1 :
                (zj == 5) ? g_X + (size_t)2 * MAT :
                (zj == 6) ? g_X + (size_t)3 * MAT : g_X;
            mm64h(As, Bs, z0, Q, nullptr, bM, bN, h, 2, 0.f, 0.f,
                  zj * 8 + (bM >> 1), (bM & 1) * 64 + h * 32);
        } else {
            int e = j - 896;
            convZ0_job(z0, e >> 2, e & 3);
        }
    }
    // no final barrier: kernel boundary orders vs fill; g_bar reset by fill.
}

// ---------------------------------------------------------------------------
// HMMA fill v3: jobs (tile, 2z), grid 8192 = 64 zgroup2 x 128 tiles
// (zg-major so concurrent CTAs share B slices in L2). 256 threads, 2 CTAs/SM.
// 3-stage cp.async pipeline (3 x 32KB: A 16K + B 16K per stage), ONE sync/iter.
// 8 chunk-iters/job; epilogue per z at c==3.
// ---------------------------------------------------------------------------
#define STAGE_BYTES 32768
#define FILL_SMEM   (3 * STAGE_BYTES)   // 96 KB

__global__ __launch_bounds__(256, 2)
void fill_kernel(float* __restrict__ out) {
    extern __shared__ __align__(128) char sm[];
    const uint32_t sbase = smem_u32(sm);
    const int tid = threadIdx.x;
    if (blockIdx.x == 0 && tid == 0) g_bar = 0;    // reset for next run's preamble
    const int zg2 = blockIdx.x >> 7;               // 0..63 (2 z each)
    const int tile = blockIdx.x & 127;
    const int tile_m = tile >> 1, tile_n = tile & 1;
    const int wid = tid >> 5, lid = tid & 31;
    const int warp_m = wid >> 2, warp_n = wid & 3;
    const int lq = lid >> 3, lr = lid & 7;
    const uint32_t a_row = warp_m * 64 + (lq & 1) * 8 + lr;
    const uint32_t b_row = warp_n * 32 + (lq & 1) * 8 + lr;
    const int gh = lq >> 1;

    // chunk idx 0..7: z = zg2*2 + (idx>>2), c = idx&3
    auto issue = [&](int idx) {
        const int z = zg2 * 2 + (idx >> 2), c = idx & 3;
        const int s = idx % 3;
        const char* a0 = (const char*)(g_ZH + (size_t)(tile_m * 4 + c) * 1024)
                         + tid * 16;
        const char* b0 = (const char*)(g_PB + (size_t)(z * 4 + c) * 2048
                                       + tile_n * 1024) + tid * 16;
        uint32_t d = sbase + s * STAGE_BYTES + tid * 16;
#pragma unroll
        for (int q = 0; q < 4; ++q) {
            CP16(d + q * 4096,         a0 + q * 4096);            // A chunk
            CP16(d + 16384 + q * 4096, b0 + q * 4096);            // B chunk
        }
        CP_COMMIT();
    };

    issue(0);
    issue(1);

    float acc[4][4][4];

    for (int idx = 0; idx < 8; ++idx) {
        if (idx < 7) CP_WAIT1(); else CP_WAIT0();
        __syncthreads();                 // single sync per iteration
        if (idx + 2 < 8) issue(idx + 2); // safe: all warps past iter idx-1

        const int c = idx & 3;
        if (c == 0) {
#pragma unroll
            for (int i = 0; i < 4; ++i)
#pragma unroll
                for (int j = 0; j < 4; ++j)
#pragma unroll
                    for (int q = 0; q < 4; ++q) acc[i][j][q] = 0.f;
        }

        const uint32_t ab  = sbase + (idx % 3) * STAGE_BYTES;
        const uint32_t bhb = ab + 16384;
#pragma unroll
        for (int ks = 0; ks < 4; ++ks) {
            const uint32_t gx = ((uint32_t)(ks * 2 + gh) ^ lr) * 16;
            uint32_t ah[4][4], bh[2][4];
#pragma unroll
            for (int mf = 0; mf < 4; ++mf)
                ldsm4(ah[mf], ab + (a_row + mf * 16) * 128 + gx);
#pragma unroll
            for (int nf = 0; nf < 2; ++nf)
                ldsm4(bh[nf], bhb + (b_row + nf * 16) * 128 + gx);
#pragma unroll
            for (int mf = 0; mf < 4; ++mf)
#pragma unroll
                for (int j = 0; j < 4; ++j) {
                    const int n2 = j >> 1, e = j & 1;
                    mma16816h(acc[mf][j], ah[mf], bh[n2][e], bh[n2][e + 2]);
                }
        }

        if (c == 3) {   // epilogue for this z (undo 2^-8 operand scaling)
            const int z = zg2 * 2 + (idx >> 2);
            const int t  = (tile_m >> 3) * CHUNK + z;
            const int b0r = (tile_m & 7) * 128 + warp_m * 64;
            const int nb = tile_n * 128 + warp_n * 32 + (lid & 3) * 2;
            const int rr = lid >> 2;
#pragma unroll
            for (int mf = 0; mf < 4; ++mf)
#pragma unroll
                for (int j = 0; j < 4; ++j) {
                    int b = b0r + mf * 16 + rr;
                    float* p0 = out + ((size_t)b * TSTEPS + t) * D + nb + j * 8;
                    float* p1 = out + ((size_t)(b + 8) * TSTEPS + t) * D + nb + j * 8;
                    *(float2*)p0 = make_float2(acc[mf][j][0] * 256.f,
                                               acc[mf][j][1] * 256.f);
                    *(float2*)p1 = make_float2(acc[mf][j][2] * 256.f,
                                               acc[mf][j][3] * 256.f);
                }
        }
    }
}

// ---------------------------------------------------------------------------
// Launch: persistent preamble -> fill
// ---------------------------------------------------------------------------
extern "C" void kernel_launch(void* const* d_in, const int* in_sizes, int n_in,
                              void* d_out, int out_size) {
    const float* z0   = (const float*)d_in[0];
    const float* kern = (const float*)d_in[1];
    float* out = (float*)d_out;
    (void)in_sizes; (void)n_in; (void)out_size;

    preamble_kernel<<<NCTA, 128>>>(z0, kern);

    cudaFuncSetAttribute(fill_kernel,
                         cudaFuncAttributeMaxDynamicSharedMemorySize, FILL_SMEM);
    fill_kernel<<<8192, 256, FILL_SMEM>>>(out);
}